// round 1
// baseline (speedup 1.0000x reference)
#include <cuda_runtime.h>

#define N_NODES 100000
#define E_EDGES 800000
#define T_TYPES 3
#define D 128

// Scratch (device globals: allocation inside kernel_launch is forbidden).
__device__ float g_xw[(size_t)T_TYPES * N_NODES * D];   // 153.6 MB: per-type x@W
__device__ int   g_deg[T_TYPES * N_NODES];
__device__ float g_dis[T_TYPES * N_NODES];

// ---------------------------------------------------------------------------
// Degree / normalization
// ---------------------------------------------------------------------------
__global__ void k_deg_init() {
    int i = blockIdx.x * blockDim.x + threadIdx.x;
    if (i < T_TYPES * N_NODES) g_deg[i] = 1;   // self-loop contributes 1
}

__global__ void k_deg_count(const int* __restrict__ edges) {
    int i = blockIdx.x * blockDim.x + threadIdx.x;
    if (i >= T_TYPES * E_EDGES) return;
    int t = i / E_EDGES;
    int e = i - t * E_EDGES;
    int dst = edges[(size_t)t * 2 * E_EDGES + E_EDGES + e];
    atomicAdd(&g_deg[t * N_NODES + dst], 1);
}

__global__ void k_dis() {
    int i = blockIdx.x * blockDim.x + threadIdx.x;
    if (i < T_TYPES * N_NODES) g_dis[i] = rsqrtf((float)g_deg[i]);
}

// ---------------------------------------------------------------------------
// GEMM: g_xw[t] = x @ W[t].  64x64 tile, K-chunks of 32, 4x4 register tiling.
// ---------------------------------------------------------------------------
__global__ void k_gemm(const float* __restrict__ x, const float* __restrict__ W) {
    const int t    = blockIdx.z;
    const int row0 = blockIdx.x * 64;
    const int col0 = blockIdx.y * 64;
    const float* Wt = W + t * D * D;
    float* xw = g_xw + (size_t)t * N_NODES * D;

    __shared__ float xs[64][33];   // pad to kill bank conflicts on column reads
    __shared__ float ws[32][64];

    const int tid = threadIdx.x;       // 0..255
    const int tx  = tid & 15;
    const int ty  = tid >> 4;

    float acc[4][4];
#pragma unroll
    for (int i = 0; i < 4; i++)
#pragma unroll
        for (int j = 0; j < 4; j++) acc[i][j] = 0.f;

    for (int k0 = 0; k0 < D; k0 += 32) {
#pragma unroll
        for (int i = 0; i < 8; i++) {          // xs: 64x32
            int idx = i * 256 + tid;
            int r = idx >> 5, c = idx & 31;
            int gr = row0 + r;
            xs[r][c] = (gr < N_NODES) ? x[(size_t)gr * D + k0 + c] : 0.f;
        }
#pragma unroll
        for (int i = 0; i < 8; i++) {          // ws: 32x64
            int idx = i * 256 + tid;
            int r = idx >> 6, c = idx & 63;
            ws[r][c] = Wt[(k0 + r) * D + col0 + c];
        }
        __syncthreads();

#pragma unroll
        for (int kk = 0; kk < 32; kk++) {
            float4 b4 = *(const float4*)&ws[kk][tx * 4];
            float a0 = xs[ty * 4 + 0][kk];
            float a1 = xs[ty * 4 + 1][kk];
            float a2 = xs[ty * 4 + 2][kk];
            float a3 = xs[ty * 4 + 3][kk];
            acc[0][0] += a0 * b4.x; acc[0][1] += a0 * b4.y; acc[0][2] += a0 * b4.z; acc[0][3] += a0 * b4.w;
            acc[1][0] += a1 * b4.x; acc[1][1] += a1 * b4.y; acc[1][2] += a1 * b4.z; acc[1][3] += a1 * b4.w;
            acc[2][0] += a2 * b4.x; acc[2][1] += a2 * b4.y; acc[2][2] += a2 * b4.z; acc[2][3] += a2 * b4.w;
            acc[3][0] += a3 * b4.x; acc[3][1] += a3 * b4.y; acc[3][2] += a3 * b4.z; acc[3][3] += a3 * b4.w;
        }
        __syncthreads();
    }

#pragma unroll
    for (int i = 0; i < 4; i++) {
        int gr = row0 + ty * 4 + i;
        if (gr < N_NODES) {
            float4 v = make_float4(acc[i][0], acc[i][1], acc[i][2], acc[i][3]);
            *(float4*)&xw[(size_t)gr * D + col0 + tx * 4] = v;
        }
    }
}

// ---------------------------------------------------------------------------
// Self-loop + bias.  Plain stores: this initializes d_out (poisoned by harness).
// out[n,:] = sum_t ( dis_t[n]^2 * xw_t[n,:] + b[t,:] )
// ---------------------------------------------------------------------------
__global__ void k_selfloop(const float* __restrict__ b, float* __restrict__ out) {
    int i = blockIdx.x * blockDim.x + threadIdx.x;   // over N*D/4 float4s
    if (i >= N_NODES * (D / 4)) return;
    int node = i / (D / 4);
    int c4   = i - node * (D / 4);
    float4 r = make_float4(0.f, 0.f, 0.f, 0.f);
#pragma unroll
    for (int t = 0; t < T_TYPES; t++) {
        float dsc = g_dis[t * N_NODES + node];
        float s = dsc * dsc;
        float4 v  = *(const float4*)&g_xw[((size_t)t * N_NODES + node) * D + c4 * 4];
        float4 bb = *(const float4*)&b[t * D + c4 * 4];
        r.x += s * v.x + bb.x;
        r.y += s * v.y + bb.y;
        r.z += s * v.z + bb.z;
        r.w += s * v.w + bb.w;
    }
    ((float4*)out)[i] = r;
}

// ---------------------------------------------------------------------------
// Edge scatter: one warp per edge, one float4 per lane (32*16B = 512B row),
// vector reduction into out[dst].  out stays L2-resident across all 3 types.
// ---------------------------------------------------------------------------
__global__ void k_scatter(const int* __restrict__ edges, float* __restrict__ out) {
    int gw   = (blockIdx.x * blockDim.x + threadIdx.x) >> 5;   // edge id
    int lane = threadIdx.x & 31;
    int t    = blockIdx.y;
    if (gw >= E_EDGES) return;

    const int* et = edges + (size_t)t * 2 * E_EDGES;
    int src = __ldg(&et[gw]);
    int dst = __ldg(&et[E_EDGES + gw]);
    float norm = g_dis[t * N_NODES + src] * g_dis[t * N_NODES + dst];

    const float4* s = (const float4*)(g_xw + ((size_t)t * N_NODES + src) * D);
    float4 v = s[lane];
    float vx = v.x * norm, vy = v.y * norm, vz = v.z * norm, vw = v.w * norm;

    float* o = out + (size_t)dst * D + lane * 4;
    asm volatile("red.global.add.v4.f32 [%0], {%1, %2, %3, %4};"
                 :: "l"(o), "f"(vx), "f"(vy), "f"(vz), "f"(vw)
                 : "memory");
}

// ---------------------------------------------------------------------------
extern "C" void kernel_launch(void* const* d_in, const int* in_sizes, int n_in,
                              void* d_out, int out_size) {
    const float* x     = (const float*)d_in[0];   // [N, 128] f32
    const int*   edges = (const int*)d_in[1];     // [3, 2, E] i32
    const float* W     = (const float*)d_in[2];   // [3, 128, 128] f32
    const float* b     = (const float*)d_in[3];   // [3, 128] f32
    float* out = (float*)d_out;                   // [N, 128] f32

    k_deg_init<<<(T_TYPES * N_NODES + 255) / 256, 256>>>();
    k_deg_count<<<(T_TYPES * E_EDGES + 255) / 256, 256>>>(edges);
    k_dis<<<(T_TYPES * N_NODES + 255) / 256, 256>>>();

    dim3 gg((N_NODES + 63) / 64, 2, 3);
    k_gemm<<<gg, 256>>>(x, W);

    k_selfloop<<<(N_NODES * (D / 4) + 255) / 256, 256>>>(b, out);

    dim3 gs((E_EDGES + 7) / 8, 3, 1);   // 8 edges (warps) per 256-thread block
    k_scatter<<<gs, 256>>>(edges, out);
}

// round 2
// speedup vs baseline: 1.0262x; 1.0262x over previous
#include <cuda_runtime.h>
#include <cuda_bf16.h>
#include <cstdint>

#define N_NODES 100000
#define E_EDGES 800000
#define T_TYPES 3
#define D 128

#define AS 136   // smem row stride in bf16 elems (272B: conflict-free frag loads)

// Scratch (device globals: allocation inside kernel_launch is forbidden).
__device__ float g_xw[(size_t)T_TYPES * N_NODES * D];   // 153.6 MB: per-type x@W
__device__ int   g_deg[T_TYPES * N_NODES];
__device__ float g_dis[T_TYPES * N_NODES];

// ---------------------------------------------------------------------------
// Degree / normalization
// ---------------------------------------------------------------------------
__global__ void k_deg_init() {
    int i = blockIdx.x * blockDim.x + threadIdx.x;
    if (i < T_TYPES * N_NODES) g_deg[i] = 1;   // self-loop contributes 1
}

__global__ void k_deg_count(const int* __restrict__ edges) {
    int i = blockIdx.x * blockDim.x + threadIdx.x;
    if (i >= T_TYPES * E_EDGES) return;
    int t = i / E_EDGES;
    int e = i - t * E_EDGES;
    int dst = edges[(size_t)t * 2 * E_EDGES + E_EDGES + e];
    atomicAdd(&g_deg[t * N_NODES + dst], 1);
}

__global__ void k_dis() {
    int i = blockIdx.x * blockDim.x + threadIdx.x;
    if (i < T_TYPES * N_NODES) g_dis[i] = rsqrtf((float)g_deg[i]);
}

// ---------------------------------------------------------------------------
// out init: out[n, c] = sum_t b[t, c]   (also un-poisons d_out)
// ---------------------------------------------------------------------------
__global__ void k_out_init(const float* __restrict__ b, float* __restrict__ out) {
    int i = blockIdx.x * blockDim.x + threadIdx.x;   // over N*32 float4s
    if (i >= N_NODES * (D / 4)) return;
    int c4 = (i & 31) * 4;
    float4 b0 = *(const float4*)&b[0 * D + c4];
    float4 b1 = *(const float4*)&b[1 * D + c4];
    float4 b2 = *(const float4*)&b[2 * D + c4];
    float4 r = make_float4(b0.x + b1.x + b2.x, b0.y + b1.y + b2.y,
                           b0.z + b1.z + b2.z, b0.w + b1.w + b2.w);
    ((float4*)out)[i] = r;
}

// ---------------------------------------------------------------------------
// Tensor-core GEMM (bf16 3-term split for fp32-grade accuracy):
//   g_xw[t] = x @ W[t];  epilogue also does out[row] += dis^2 * xw[row] (self loop)
// CTA tile: 128 rows x 128 cols, K=128 in one shot. 8 warps: 4(m) x 2(n),
// warp tile 32x64 via mma.sync m16n8k16 bf16.
// ---------------------------------------------------------------------------
__device__ __forceinline__ void split_bf16(float a, __nv_bfloat16& h, __nv_bfloat16& l) {
    h = __float2bfloat16(a);
    l = __float2bfloat16(a - __bfloat162float(h));
}

#define MMA_BF16(d, a, b)                                                     \
    asm volatile("mma.sync.aligned.m16n8k16.row.col.f32.bf16.bf16.f32 "       \
                 "{%0,%1,%2,%3}, {%4,%5,%6,%7}, {%8,%9}, {%0,%1,%2,%3};"      \
                 : "+f"(d[0]), "+f"(d[1]), "+f"(d[2]), "+f"(d[3])             \
                 : "r"(a[0]), "r"(a[1]), "r"(a[2]), "r"(a[3]),                \
                   "r"(b[0]), "r"(b[1]))

__global__ void k_gemm(const float* __restrict__ x, const float* __restrict__ W,
                       float* __restrict__ out) {
    extern __shared__ char smem[];
    __nv_bfloat16* As_hi = (__nv_bfloat16*)smem;                 // [128][AS]
    __nv_bfloat16* As_lo = As_hi + 128 * AS;
    __nv_bfloat16* Bs_hi = As_lo + 128 * AS;                     // [n=128][k=AS]
    __nv_bfloat16* Bs_lo = Bs_hi + 128 * AS;
    float*         dis_s = (float*)(smem + (size_t)4 * 128 * AS * 2);

    const int tid  = threadIdx.x;
    const int t    = blockIdx.z;
    const int row0 = blockIdx.x * 128;
    const float* Wt = W + t * D * D;
    float* xw = g_xw + (size_t)t * N_NODES * D;

    // ---- load x tile [128 x 128] f32 -> hi/lo bf16, row-major ----
#pragma unroll
    for (int i = 0; i < 16; i++) {
        int idx = i * 256 + tid;            // 0..4095 float4s
        int r = idx >> 5, c4 = idx & 31;
        float4 v = make_float4(0.f, 0.f, 0.f, 0.f);
        int gr = row0 + r;
        if (gr < N_NODES) v = *(const float4*)&x[(size_t)gr * D + c4 * 4];
        __nv_bfloat16 h0, h1, h2, h3, l0, l1, l2, l3;
        split_bf16(v.x, h0, l0); split_bf16(v.y, h1, l1);
        split_bf16(v.z, h2, l2); split_bf16(v.w, h3, l3);
        __nv_bfloat162 ph0, ph1, pl0, pl1;
        ph0.x = h0; ph0.y = h1; ph1.x = h2; ph1.y = h3;
        pl0.x = l0; pl0.y = l1; pl1.x = l2; pl1.y = l3;
        __nv_bfloat162* dh = (__nv_bfloat162*)&As_hi[r * AS + c4 * 4];
        __nv_bfloat162* dl = (__nv_bfloat162*)&As_lo[r * AS + c4 * 4];
        dh[0] = ph0; dh[1] = ph1;
        dl[0] = pl0; dl[1] = pl1;
    }
    // ---- load W[t] [k=128 x n=128] -> transposed smem [n][k], hi/lo ----
#pragma unroll
    for (int i = 0; i < 16; i++) {
        int idx = i * 256 + tid;
        int k = idx >> 5, c4 = idx & 31;
        float4 v = *(const float4*)&Wt[k * D + c4 * 4];
        float vv[4] = {v.x, v.y, v.z, v.w};
#pragma unroll
        for (int j = 0; j < 4; j++) {
            int n = c4 * 4 + j;
            __nv_bfloat16 h, l;
            split_bf16(vv[j], h, l);
            Bs_hi[n * AS + k] = h;
            Bs_lo[n * AS + k] = l;
        }
    }
    if (tid < 128) {
        int gr = row0 + tid;
        dis_s[tid] = (gr < N_NODES) ? g_dis[t * N_NODES + gr] : 0.f;
    }
    __syncthreads();

    const int lane = tid & 31, warp = tid >> 5;
    const int wm = warp & 3, wn = warp >> 2;   // warp tile: rows wm*32..+32, cols wn*64..+64
    const int qr = lane >> 2;                  // 0..7
    const int qc = lane & 3;                   // 0..3

    float acc[2][8][4];
#pragma unroll
    for (int mt = 0; mt < 2; mt++)
#pragma unroll
        for (int nt = 0; nt < 8; nt++)
#pragma unroll
            for (int j = 0; j < 4; j++) acc[mt][nt][j] = 0.f;

#pragma unroll
    for (int ks = 0; ks < 8; ks++) {
        const int k0 = ks * 16 + qc * 2;
        uint32_t ah[2][4], al[2][4];
#pragma unroll
        for (int mt = 0; mt < 2; mt++) {
            int r = wm * 32 + mt * 16 + qr;
            const __nv_bfloat16* ph = &As_hi[r * AS + k0];
            ah[mt][0] = *(const uint32_t*)(ph);
            ah[mt][1] = *(const uint32_t*)(ph + 8 * AS);
            ah[mt][2] = *(const uint32_t*)(ph + 8);
            ah[mt][3] = *(const uint32_t*)(ph + 8 * AS + 8);
            const __nv_bfloat16* pl = &As_lo[r * AS + k0];
            al[mt][0] = *(const uint32_t*)(pl);
            al[mt][1] = *(const uint32_t*)(pl + 8 * AS);
            al[mt][2] = *(const uint32_t*)(pl + 8);
            al[mt][3] = *(const uint32_t*)(pl + 8 * AS + 8);
        }
#pragma unroll
        for (int nt = 0; nt < 8; nt++) {
            int n = wn * 64 + nt * 8 + qr;
            const __nv_bfloat16* pbh = &Bs_hi[n * AS + k0];
            const __nv_bfloat16* pbl = &Bs_lo[n * AS + k0];
            uint32_t bh[2] = {*(const uint32_t*)pbh, *(const uint32_t*)(pbh + 8)};
            uint32_t bl[2] = {*(const uint32_t*)pbl, *(const uint32_t*)(pbl + 8)};
#pragma unroll
            for (int mt = 0; mt < 2; mt++) {
                MMA_BF16(acc[mt][nt], ah[mt], bh);
                MMA_BF16(acc[mt][nt], ah[mt], bl);
                MMA_BF16(acc[mt][nt], al[mt], bh);
            }
        }
    }

    // ---- epilogue: store xw + self-loop red-add of dis^2 * xw into out ----
#pragma unroll
    for (int mt = 0; mt < 2; mt++) {
        int rl0 = wm * 32 + mt * 16 + qr;
        int rl1 = rl0 + 8;
        int gr0 = row0 + rl0, gr1 = row0 + rl1;
        float s0 = dis_s[rl0]; s0 *= s0;
        float s1 = dis_s[rl1]; s1 *= s1;
#pragma unroll
        for (int nt = 0; nt < 8; nt++) {
            int col = wn * 64 + nt * 8 + qc * 2;
            if (gr0 < N_NODES) {
                float2 v = make_float2(acc[mt][nt][0], acc[mt][nt][1]);
                *(float2*)&xw[(size_t)gr0 * D + col] = v;
                float* p = out + (size_t)gr0 * D + col;
                asm volatile("red.global.add.v2.f32 [%0], {%1,%2};"
                             :: "l"(p), "f"(s0 * v.x), "f"(s0 * v.y) : "memory");
            }
            if (gr1 < N_NODES) {
                float2 v = make_float2(acc[mt][nt][2], acc[mt][nt][3]);
                *(float2*)&xw[(size_t)gr1 * D + col] = v;
                float* p = out + (size_t)gr1 * D + col;
                asm volatile("red.global.add.v2.f32 [%0], {%1,%2};"
                             :: "l"(p), "f"(s1 * v.x), "f"(s1 * v.y) : "memory");
            }
        }
    }
}

// ---------------------------------------------------------------------------
// Edge scatter: one warp per edge, one float4 per lane (32*16B = 512B row),
// vector reduction into out[dst].  out stays L2-resident across all 3 types.
// ---------------------------------------------------------------------------
__global__ void k_scatter(const int* __restrict__ edges, float* __restrict__ out) {
    int gw   = (blockIdx.x * blockDim.x + threadIdx.x) >> 5;   // edge id
    int lane = threadIdx.x & 31;
    int t    = blockIdx.y;
    if (gw >= E_EDGES) return;

    const int* et = edges + (size_t)t * 2 * E_EDGES;
    int src = __ldg(&et[gw]);
    int dst = __ldg(&et[E_EDGES + gw]);
    float norm = g_dis[t * N_NODES + src] * g_dis[t * N_NODES + dst];

    const float4* s = (const float4*)(g_xw + ((size_t)t * N_NODES + src) * D);
    float4 v = s[lane];
    float vx = v.x * norm, vy = v.y * norm, vz = v.z * norm, vw = v.w * norm;

    float* o = out + (size_t)dst * D + lane * 4;
    asm volatile("red.global.add.v4.f32 [%0], {%1, %2, %3, %4};"
                 :: "l"(o), "f"(vx), "f"(vy), "f"(vz), "f"(vw)
                 : "memory");
}

// ---------------------------------------------------------------------------
extern "C" void kernel_launch(void* const* d_in, const int* in_sizes, int n_in,
                              void* d_out, int out_size) {
    const float* x     = (const float*)d_in[0];   // [N, 128] f32
    const int*   edges = (const int*)d_in[1];     // [3, 2, E] i32
    const float* W     = (const float*)d_in[2];   // [3, 128, 128] f32
    const float* b     = (const float*)d_in[3];   // [3, 128] f32
    float* out = (float*)d_out;                   // [N, 128] f32

    const int smem_bytes = 4 * 128 * AS * 2 + 512;   // 139264 + 512
    static bool attr_set = false;
    // (idempotent; executes immediately, not a stream op, so capture-safe)
    cudaFuncSetAttribute(k_gemm, cudaFuncAttributeMaxDynamicSharedMemorySize, smem_bytes);
    (void)attr_set;

    k_deg_init<<<(T_TYPES * N_NODES + 255) / 256, 256>>>();
    k_deg_count<<<(T_TYPES * E_EDGES + 255) / 256, 256>>>(edges);
    k_dis<<<(T_TYPES * N_NODES + 255) / 256, 256>>>();

    k_out_init<<<(N_NODES * (D / 4) + 255) / 256, 256>>>(b, out);

    dim3 gg((N_NODES + 127) / 128, 1, 3);
    k_gemm<<<gg, 256, smem_bytes>>>(x, W, out);

    dim3 gs((E_EDGES + 7) / 8, 3, 1);   // 8 edges (warps) per 256-thread block
    k_scatter<<<gs, 256>>>(edges, out);
}

// round 4
// speedup vs baseline: 1.9094x; 1.8606x over previous
#include <cuda_runtime.h>
#include <cuda_bf16.h>
#include <cuda_fp16.h>
#include <cstdint>

#define NN 100000
#define EE 800000
#define TT 3
#define D  128
#define TND (TT * NN)
#define NCTA 782           // ceil(NN/128)
#define BSTRIDE 136        // smem row stride in bf16 elems (272B, ldmatrix conflict-free)
#define TILE_BYTES 34816   // 128 * 272

// ---------------- device scratch (no allocs allowed) ----------------
__device__ __half g_xwh[(size_t)TT * NN * D];       // 76.8 MB fp16 xw (gather feed)
__device__ uint4  g_wb[TT * 2 * (TILE_BYTES / 16)]; // W hi/lo pre-baked smem images
__device__ int    g_deg[TND];
__device__ float  g_dis[TND];
__device__ int    g_off[TND];
__device__ int    g_cur[TND];
__device__ int    g_part[1024];
__device__ int    g_csr[TT * EE];

// ---------------- helpers ----------------
__device__ __forceinline__ uint32_t smem_u32(const void* p) {
    uint32_t a;
    asm("{ .reg .u64 t; cvta.to.shared.u64 t, %1; cvt.u32.u64 %0, t; }" : "=r"(a) : "l"(p));
    return a;
}
__device__ __forceinline__ void split2(float a, __nv_bfloat16& h, __nv_bfloat16& l) {
    h = __float2bfloat16(a);
    l = __float2bfloat16(a - __bfloat162float(h));
}
__device__ __forceinline__ uint32_t packbf(__nv_bfloat16 a, __nv_bfloat16 b) {
    __nv_bfloat162 p; p.x = a; p.y = b;
    return *(uint32_t*)&p;
}

#define LDSM4(r0, r1, r2, r3, addr)                                              \
    asm volatile("ldmatrix.sync.aligned.m8n8.x4.shared.b16 {%0,%1,%2,%3}, [%4];" \
                 : "=r"(r0), "=r"(r1), "=r"(r2), "=r"(r3) : "r"(addr))

#define MMA_BF16(d, a0, a1, a2, a3, b0, b1)                                   \
    asm volatile("mma.sync.aligned.m16n8k16.row.col.f32.bf16.bf16.f32 "       \
                 "{%0,%1,%2,%3}, {%4,%5,%6,%7}, {%8,%9}, {%0,%1,%2,%3};"      \
                 : "+f"(d[0]), "+f"(d[1]), "+f"(d[2]), "+f"(d[3])             \
                 : "r"(a0), "r"(a1), "r"(a2), "r"(a3), "r"(b0), "r"(b1))

// ---------------- degree / norm ----------------
__global__ void k_deg_init() {
    int i = blockIdx.x * blockDim.x + threadIdx.x;
    if (i < TND) g_deg[i] = 1;   // self loop
}
__global__ void k_deg_count(const int* __restrict__ edges) {
    int i = blockIdx.x * blockDim.x + threadIdx.x;
    if (i >= TT * EE) return;
    int t = i / EE, e = i - t * EE;
    int dst = edges[(size_t)t * 2 * EE + EE + e];
    atomicAdd(&g_deg[t * NN + dst], 1);
}
__global__ void k_dis() {
    int i = blockIdx.x * blockDim.x + threadIdx.x;
    if (i < TND) g_dis[i] = rsqrtf((float)g_deg[i]);
}

// ---------------- CSR build: scan of (deg-1), then fill ----------------
__global__ void k_scan1() {   // 512/block, 586 blocks
    __shared__ int s[512];
    int t = threadIdx.x, i = blockIdx.x * 512 + t;
    int v = (i < TND) ? (g_deg[i] - 1) : 0;
    s[t] = v;
    __syncthreads();
#pragma unroll
    for (int off = 1; off < 512; off <<= 1) {
        int add = (t >= off) ? s[t - off] : 0;
        __syncthreads();
        s[t] += add;
        __syncthreads();
    }
    if (i < TND) g_off[i] = s[t] - v;      // exclusive, block-local
    if (t == 511) g_part[blockIdx.x] = s[511];
}
__global__ void k_scan2() {   // 1 block, 1024 threads (586 partials)
    __shared__ int s[1024];
    int t = threadIdx.x;
    int v = (t < 586) ? g_part[t] : 0;
    s[t] = v;
    __syncthreads();
#pragma unroll
    for (int off = 1; off < 1024; off <<= 1) {
        int add = (t >= off) ? s[t - off] : 0;
        __syncthreads();
        s[t] += add;
        __syncthreads();
    }
    if (t < 586) g_part[t] = s[t] - v;     // exclusive
}
__global__ void k_scan3() {
    int i = blockIdx.x * blockDim.x + threadIdx.x;
    if (i >= TND) return;
    int v = g_off[i] + g_part[i >> 9];
    g_off[i] = v;
    g_cur[i] = v;
}
__global__ void k_csr_fill(const int* __restrict__ edges) {
    int i = blockIdx.x * blockDim.x + threadIdx.x;
    if (i >= TT * EE) return;
    int t = i / EE, e = i - t * EE;
    int src = edges[(size_t)t * 2 * EE + e];
    int dst = edges[(size_t)t * 2 * EE + EE + e];
    int pos = atomicAdd(&g_cur[t * NN + dst], 1);
    g_csr[pos] = src;
}

// ---------------- W prebake: hi/lo bf16 in [n][k] stride-136 smem image ----------------
__global__ void k_split_w(const float* __restrict__ W) {
    int i = blockIdx.x * blockDim.x + threadIdx.x;   // 3*128*32 float4s
    if (i >= TT * 128 * 32) return;
    int t = i / (128 * 32);
    int k = (i >> 5) & 127;
    int c4 = i & 31;
    float4 v = *(const float4*)&W[(size_t)t * D * D + k * D + c4 * 4];
    float vv[4] = {v.x, v.y, v.z, v.w};
    unsigned char* hi = (unsigned char*)g_wb + (size_t)(t * 2 + 0) * TILE_BYTES;
    unsigned char* lo = (unsigned char*)g_wb + (size_t)(t * 2 + 1) * TILE_BYTES;
#pragma unroll
    for (int j = 0; j < 4; j++) {
        int n = c4 * 4 + j;
        __nv_bfloat16 h, l;
        split2(vv[j], h, l);
        *(__nv_bfloat16*)(hi + (size_t)n * 272 + k * 2) = h;
        *(__nv_bfloat16*)(lo + (size_t)n * 272 + k * 2) = l;
    }
}

// ---------------- GEMM: xw[t] = x @ W[t], bf16 3-term split, ldmatrix + mma.sync ----------
// smem: A_hi[0,34816) A_lo[34816,69632) B_hi[69632,104448) B_lo[104448,139264)
// B_hi region reused as fp16 output stage per t.
#define SM_AL 34816u
#define SM_B  69632u
#define SM_BL 104448u
#define SMEM_BYTES 139264u

__global__ void __launch_bounds__(256, 1) k_gemm(const float* __restrict__ x) {
    extern __shared__ char sm[];
    uint32_t sb = smem_u32(sm);
    const int tid = threadIdx.x, lane = tid & 31, warp = tid >> 5;
    const int row0 = blockIdx.x * 128;
    const int wm = warp & 3, wn = warp >> 2;
    const int qr = lane >> 2, qc = lane & 3;

    // ---- A load + hi/lo split (once, reused for all 3 relations) ----
    for (int i = tid; i < 4096; i += 256) {
        int r = i >> 5, c4 = i & 31;
        int gr = row0 + r;
        float4 v = make_float4(0.f, 0.f, 0.f, 0.f);
        if (gr < NN) v = *(const float4*)&x[(size_t)gr * D + c4 * 4];
        __nv_bfloat16 h0, h1, h2, h3, l0, l1, l2, l3;
        split2(v.x, h0, l0); split2(v.y, h1, l1);
        split2(v.z, h2, l2); split2(v.w, h3, l3);
        uint2 hv = make_uint2(packbf(h0, h1), packbf(h2, h3));
        uint2 lv = make_uint2(packbf(l0, l1), packbf(l2, l3));
        uint32_t o = (uint32_t)r * 272 + c4 * 8;
        *(uint2*)(sm + o)         = hv;
        *(uint2*)(sm + SM_AL + o) = lv;
    }

    // ldmatrix lane address components (bytes)
    const uint32_t aoff = sb + (uint32_t)(wm * 32 + (lane & 15)) * 272 + (lane >> 4) * 16;
    const uint32_t boff = sb + SM_B +
        (uint32_t)(wn * 64 + ((lane >> 3) & 1) * 8 + (lane & 7)) * 272 + (lane >> 4) * 16;

    for (int t = 0; t < TT; t++) {
        __syncthreads();   // A ready (t=0) / stage copy of prev t done
        // B tiles: raw copy of pre-baked image (hi + lo contiguous)
        const uint4* bsrc = g_wb + (size_t)t * 2 * (TILE_BYTES / 16);
        for (int i = tid; i < 2 * (TILE_BYTES / 16); i += 256)
            ((uint4*)(sm + SM_B))[i] = bsrc[i];
        __syncthreads();

        float acc[2][8][4];
#pragma unroll
        for (int mt = 0; mt < 2; mt++)
#pragma unroll
            for (int nt = 0; nt < 8; nt++)
#pragma unroll
                for (int j = 0; j < 4; j++) acc[mt][nt][j] = 0.f;

#pragma unroll
        for (int ks = 0; ks < 8; ks++) {
            uint32_t ah[2][4], al[2][4];
#pragma unroll
            for (int mt = 0; mt < 2; mt++) {
                uint32_t a = aoff + mt * 4352 + ks * 32;
                LDSM4(ah[mt][0], ah[mt][1], ah[mt][2], ah[mt][3], a);
                LDSM4(al[mt][0], al[mt][1], al[mt][2], al[mt][3], a + SM_AL);
            }
#pragma unroll
            for (int j = 0; j < 4; j++) {
                uint32_t ba = boff + j * 4352 + ks * 32;
                uint32_t bh[4], bl[4];
                LDSM4(bh[0], bh[1], bh[2], bh[3], ba);
                LDSM4(bl[0], bl[1], bl[2], bl[3], ba + TILE_BYTES);
                // matrices: r0=(nt=2j,k0) r1=(2j+1,k0) r2=(2j,k8) r3=(2j+1,k8)
#pragma unroll
                for (int mt = 0; mt < 2; mt++) {
                    MMA_BF16(acc[mt][2 * j],     ah[mt][0], ah[mt][1], ah[mt][2], ah[mt][3], bh[0], bh[2]);
                    MMA_BF16(acc[mt][2 * j],     ah[mt][0], ah[mt][1], ah[mt][2], ah[mt][3], bl[0], bl[2]);
                    MMA_BF16(acc[mt][2 * j],     al[mt][0], al[mt][1], al[mt][2], al[mt][3], bh[0], bh[2]);
                    MMA_BF16(acc[mt][2 * j + 1], ah[mt][0], ah[mt][1], ah[mt][2], ah[mt][3], bh[1], bh[3]);
                    MMA_BF16(acc[mt][2 * j + 1], ah[mt][0], ah[mt][1], ah[mt][2], ah[mt][3], bl[1], bl[3]);
                    MMA_BF16(acc[mt][2 * j + 1], al[mt][0], al[mt][1], al[mt][2], al[mt][3], bh[1], bh[3]);
                }
            }
        }

        // ---- epilogue: fp16 stage in B_hi region, then coalesced copy out ----
        __syncthreads();   // all warps done reading B smem
#pragma unroll
        for (int mt = 0; mt < 2; mt++) {
            int r0 = wm * 32 + mt * 16 + qr;
#pragma unroll
            for (int nt = 0; nt < 8; nt++) {
                int col = wn * 64 + nt * 8 + qc * 2;
                *(__half2*)(sm + SM_B + (uint32_t)r0 * 272 + col * 2) =
                    __float22half2_rn(make_float2(acc[mt][nt][0], acc[mt][nt][1]));
                *(__half2*)(sm + SM_B + (uint32_t)(r0 + 8) * 272 + col * 2) =
                    __float22half2_rn(make_float2(acc[mt][nt][2], acc[mt][nt][3]));
            }
        }
        __syncthreads();
        for (int i = tid; i < 2048; i += 256) {
            int r = i >> 4, j = i & 15;
            int gr = row0 + r;
            if (gr < NN)
                *(uint4*)(g_xwh + ((size_t)t * NN + gr) * D + j * 8) =
                    *(uint4*)(sm + SM_B + (uint32_t)r * 272 + j * 16);
        }
    }
}

// ---------------- gather: one warp per node, all types, plain store ----------------
__global__ void k_gather(const float* __restrict__ b, float* __restrict__ out) {
    int w    = (blockIdx.x * blockDim.x + threadIdx.x) >> 5;   // node id
    int lane = threadIdx.x & 31;
    if (w >= NN) return;

    float ax, ay, az, aw;
    {
        float4 b0 = *(const float4*)&b[0 * D + lane * 4];
        float4 b1 = *(const float4*)&b[1 * D + lane * 4];
        float4 b2 = *(const float4*)&b[2 * D + lane * 4];
        ax = b0.x + b1.x + b2.x; ay = b0.y + b1.y + b2.y;
        az = b0.z + b1.z + b2.z; aw = b0.w + b1.w + b2.w;
    }

#pragma unroll
    for (int t = 0; t < TT; t++) {
        const __half* xb = g_xwh + (size_t)t * NN * D;
        float dn = g_dis[t * NN + w];

        // self loop: dn^2 * xw[w]
        {
            uint2 v = *(const uint2*)(xb + (size_t)w * D + lane * 4);
            __half2* h2 = (__half2*)&v;
            float2 f0 = __half22float2(h2[0]);
            float2 f1 = __half22float2(h2[1]);
            float s = dn * dn;
            ax += s * f0.x; ay += s * f0.y; az += s * f1.x; aw += s * f1.y;
        }

        int st  = g_off[t * NN + w];
        int cnt = g_deg[t * NN + w] - 1;
#pragma unroll 4
        for (int e = 0; e < cnt; e++) {
            int src  = __ldg(&g_csr[st + e]);
            float nr = dn * __ldg(&g_dis[t * NN + src]);
            uint2 v  = *(const uint2*)(xb + (size_t)src * D + lane * 4);
            __half2* h2 = (__half2*)&v;
            float2 f0 = __half22float2(h2[0]);
            float2 f1 = __half22float2(h2[1]);
            ax += nr * f0.x; ay += nr * f0.y; az += nr * f1.x; aw += nr * f1.y;
        }
    }
    *(float4*)&out[(size_t)w * D + lane * 4] = make_float4(ax, ay, az, aw);
}

// ---------------------------------------------------------------------------
extern "C" void kernel_launch(void* const* d_in, const int* in_sizes, int n_in,
                              void* d_out, int out_size) {
    const float* x     = (const float*)d_in[0];   // [N, 128] f32
    const int*   edges = (const int*)d_in[1];     // [3, 2, E] i32
    const float* W     = (const float*)d_in[2];   // [3, 128, 128] f32
    const float* b     = (const float*)d_in[3];   // [3, 128] f32
    float* out = (float*)d_out;                   // [N, 128] f32

    cudaFuncSetAttribute(k_gemm, cudaFuncAttributeMaxDynamicSharedMemorySize, SMEM_BYTES);

    k_deg_init<<<(TND + 255) / 256, 256>>>();
    k_deg_count<<<(TT * EE + 255) / 256, 256>>>(edges);
    k_dis<<<(TND + 255) / 256, 256>>>();

    k_scan1<<<(TND + 511) / 512, 512>>>();
    k_scan2<<<1, 1024>>>();
    k_scan3<<<(TND + 255) / 256, 256>>>();
    k_csr_fill<<<(TT * EE + 255) / 256, 256>>>(edges);

    k_split_w<<<(TT * 128 * 32 + 255) / 256, 256>>>(W);
    k_gemm<<<NCTA, 256, SMEM_BYTES>>>(x);

    k_gather<<<(NN * 32 + 255) / 256, 256>>>(b, out);
}